// round 6
// baseline (speedup 1.0000x reference)
#include <cuda_runtime.h>

#define TT 512
#define BB 256

__device__ float H1buf[(TT + 1) * BB * 64];
__device__ float H2buf[(TT + 1) * BB * 128];
__device__ float H3buf[(TT + 1) * BB * 256];
// k3 per-group barrier state (monotonic; survives graph replays)
__device__ unsigned k3_sub[4 * 4 * 32];
__device__ unsigned k3_root[4 * 32];
__device__ unsigned k3_rel[4 * 32];

// out offsets
#define OFF_Y  0
#define OFF_H1 (TT*BB)
#define OFF_H2 (OFF_H1 + BB*64)
#define OFF_H3 (OFF_H2 + BB*128)
#define OFF_C1 (OFF_H3 + BB*256)
#define OFF_C2 (OFF_C1 + BB*64)
#define OFF_C3 (OFF_C2 + BB*128)

__device__ __forceinline__ float ex2f(float x){float y;asm("ex2.approx.f32 %0,%1;":"=f"(y):"f"(x));return y;}
__device__ __forceinline__ float rcpf(float x){float y;asm("rcp.approx.f32 %0,%1;":"=f"(y):"f"(x));return y;}
__device__ __forceinline__ float sigf(float x){return rcpf(1.0f+ex2f(-1.4426950408889634f*x));}
__device__ __forceinline__ float tanhf_(float x){return 2.0f*rcpf(1.0f+ex2f(-2.8853900817779268f*x))-1.0f;}

__device__ __forceinline__ unsigned long long ffma2(unsigned long long a, unsigned long long b, unsigned long long c){
    unsigned long long d;
    asm("fma.rn.f32x2 %0,%1,%2,%3;" : "=l"(d) : "l"(a), "l"(b), "l"(c));
    return d;
}
__device__ __forceinline__ float fsum2(unsigned long long v){
    float lo, hi;
    asm("mov.b64 {%0,%1},%2;" : "=f"(lo), "=f"(hi) : "l"(v));
    return lo + hi;
}
__device__ __forceinline__ void cpa16(unsigned s, const void* g){
    asm volatile("cp.async.cg.shared.global [%0],[%1],16;" :: "r"(s), "l"(g));
}
#define CP_COMMIT() asm volatile("cp.async.commit_group;" ::: "memory")
#define CP_WAIT1()  asm volatile("cp.async.wait_group 1;" ::: "memory")
__device__ __forceinline__ unsigned smem_u32(const void* p){
    unsigned a;
    asm("{ .reg .u64 t; cvta.to.shared.u64 t,%1; cvt.u32.u64 %0,t; }" : "=r"(a) : "l"(p));
    return a;
}
__device__ __forceinline__ unsigned ctarank(){
    unsigned r; asm("mov.u32 %0,%%cluster_ctarank;" : "=r"(r)); return r;
}
__device__ __forceinline__ unsigned mapa_peer(unsigned laddr, unsigned rank){
    unsigned r; asm("mapa.shared::cluster.u32 %0,%1,%2;" : "=r"(r) : "r"(laddr), "r"(rank)); return r;
}
__device__ __forceinline__ void st_remote(unsigned addr, float v){
    asm volatile("st.shared::cluster.f32 [%0],%1;" :: "r"(addr), "f"(v));
}
#define CLUSTER_SYNC() do{ \
    asm volatile("barrier.cluster.arrive.aligned;" ::: "memory"); \
    asm volatile("barrier.cluster.wait.aligned;" ::: "memory"); }while(0)

// per-group (32 CTA) two-level monotonic barrier for k3
__device__ __forceinline__ void gbar3(int tid, int grp, int sub){
    __syncthreads();
    if (tid == 0){
        unsigned* rel = &k3_rel[grp * 32];
        unsigned r0;
        asm volatile("ld.relaxed.gpu.u32 %0,[%1];" : "=r"(r0) : "l"(rel));
        __threadfence();
        bool done = false;
        unsigned og = atomicAdd(&k3_sub[(grp * 4 + sub) * 32], 1u);
        if ((og & 7u) == 7u){
            unsigned orr = atomicAdd(&k3_root[grp * 32], 1u);
            if ((orr & 3u) == 3u){
                asm volatile("st.release.gpu.u32 [%0],%1;" :: "l"(rel), "r"(r0 + 1u) : "memory");
                done = true;
            }
        }
        if (!done){
            unsigned v;
            do { __nanosleep(20);
                 asm volatile("ld.acquire.gpu.u32 %0,[%1];" : "=r"(v) : "l"(rel) : "memory");
            } while (v == r0);
        }
    }
    __syncthreads();
}

// ===================== k1: layer-1 full recurrence, batch-partitioned =====================
#define K1_W   0
#define K1_WI  17408
#define K1_B   17664
#define K1_X   17920
#define K1_H   18944
#define K1_G   19072
#define K1_FL  19584

__global__ void __launch_bounds__(256,1) k1_l1(
    const float* __restrict__ x, const float* __restrict__ h1in, const float* __restrict__ c1in,
    const float* __restrict__ Wih1, const float* __restrict__ Whh1,
    const float* __restrict__ bih1, const float* __restrict__ bhh1,
    float* __restrict__ out)
{
    extern __shared__ float sm[];
    const int tid = threadIdx.x;
    const int b0 = blockIdx.x * 2;

    for (int i = tid; i < 256*64; i += 256)
        sm[K1_W + (i>>6)*68 + (i&63)] = Whh1[i];
    if (tid < 256){
        sm[K1_WI + tid] = Wih1[tid];
        sm[K1_B + tid] = bih1[tid] + bhh1[tid];
    }
    for (int i = tid; i < 1024; i += 256)
        sm[K1_X + i] = x[(i>>1)*BB + b0 + (i&1)];
    if (tid < 128)
        sm[K1_H + tid] = h1in[(b0 + (tid>>6))*64 + (tid&63)];
    float creg = 0.0f;
    if (tid < 128) creg = c1in[(b0 + (tid>>6))*64 + (tid&63)];
    __syncthreads();

    for (int t = 0; t < TT; t++){
        unsigned long long q0 = 0ull, q1 = 0ull;
#pragma unroll
        for (int kq = 0; kq < 16; kq++){
            ulonglong2 w  = *(const ulonglong2*)&sm[K1_W + tid*68 + kq*4];
            ulonglong2 h0 = *(const ulonglong2*)&sm[K1_H + kq*4];
            ulonglong2 h1 = *(const ulonglong2*)&sm[K1_H + 64 + kq*4];
            q0 = ffma2(w.x, h0.x, q0); q0 = ffma2(w.y, h0.y, q0);
            q1 = ffma2(w.x, h1.x, q1); q1 = ffma2(w.y, h1.y, q1);
        }
        float bb = sm[K1_B + tid], wi = sm[K1_WI + tid];
        sm[K1_G + tid*2]     = fsum2(q0) + bb + wi * sm[K1_X + t*2];
        sm[K1_G + tid*2 + 1] = fsum2(q1) + bb + wi * sm[K1_X + t*2 + 1];
        __syncthreads();
        if (tid < 128){
            const int j = tid & 63, row = tid >> 6;
            float iv = sigf(sm[K1_G + (j)*2 + row]);
            float fv = sigf(sm[K1_G + (64+j)*2 + row]);
            float gv = tanhf_(sm[K1_G + (128+j)*2 + row]);
            float ov = sigf(sm[K1_G + (192+j)*2 + row]);
            float c = fv * creg + iv * gv; creg = c;
            float hv = ov * tanhf_(c);
            sm[K1_H + row*64 + j] = hv;
            __stcg(&H1buf[(size_t)t*BB*64 + (b0+row)*64 + j], hv);
        }
        __syncthreads();
    }
    if (tid < 128){
        const int j = tid & 63, row = tid >> 6;
        out[OFF_C1 + (b0+row)*64 + j] = creg;
        out[OFF_H1 + (b0+row)*64 + j] = sm[K1_H + row*64 + j];
    }
}

// ===================== k2: layer-2 recurrence, 2-CTA clusters =====================
#define K2_WH 0
#define K2_WI 33792
#define K2_B  51200
#define K2_H  51456
#define K2_H1 51968
#define K2_G  52480
#define K2_FL 53504

__global__ void __launch_bounds__(256,1) __cluster_dims__(2,1,1) k2_l2(
    const float* __restrict__ h2in, const float* __restrict__ c2in,
    const float* __restrict__ Wih2, const float* __restrict__ Whh2,
    const float* __restrict__ bih2, const float* __restrict__ bhh2,
    float* __restrict__ out)
{
    extern __shared__ float sm[];
    const unsigned smb = smem_u32(sm);
    const int tid = threadIdx.x;
    const unsigned r = ctarank();
    const int b0 = (blockIdx.x >> 1) * 4;
    const int d0 = (int)r * 64;

    // weights: local gate-row lr = g*64 + j  -> global row g*128 + d0 + j
    for (int i = tid; i < 256*128; i += 256){
        int lr = i >> 7, k = i & 127;
        int gr = (lr >> 6)*128 + d0 + (lr & 63);
        sm[K2_WH + lr*132 + k] = Whh2[gr*128 + k];
    }
    for (int i = tid; i < 256*64; i += 256){
        int lr = i >> 6, k = i & 63;
        int gr = (lr >> 6)*128 + d0 + (lr & 63);
        sm[K2_WI + lr*68 + k] = Wih2[gr*64 + k];
    }
    if (tid < 256){
        int gr = (tid >> 6)*128 + d0 + (tid & 63);
        sm[K2_B + tid] = bih2[gr] + bhh2[gr];
    }
    for (int i = tid; i < 512; i += 256)
        sm[K2_H + i] = h2in[(b0 + (i>>7))*128 + (i & 127)];
    const int cj = tid & 63, crow = tid >> 6;
    float creg = c2in[(b0+crow)*128 + d0 + cj];
    const unsigned peer_h = mapa_peer(smb + (unsigned)K2_H*4u, r ^ 1u);

    // prefetch h1[0] (H1buf rows b0..b0+3 contiguous: 256 floats)
    for (int i = tid; i < 64; i += 256)
        cpa16(smb + (unsigned)(K2_H1 + i*4)*4u, &H1buf[0 + b0*64 + i*4]);
    CP_COMMIT();
    __syncthreads();
    CLUSTER_SYNC();

    for (int t = 0; t < TT; t++){
        if (t < TT-1){
            const float* gp = &H1buf[(size_t)(t+1)*BB*64 + b0*64];
            for (int i = tid; i < 64; i += 256)
                cpa16(smb + (unsigned)(K2_H1 + ((t+1)&1)*256 + i*4)*4u, gp + i*4);
        }
        CP_COMMIT();
        CP_WAIT1();
        __syncthreads();
        const float* h1s = &sm[K2_H1 + (t&1)*256];

        unsigned long long q0=0ull,q1=0ull,q2=0ull,q3=0ull;
#pragma unroll 4
        for (int kq = 0; kq < 32; kq++){
            ulonglong2 w  = *(const ulonglong2*)&sm[K2_WH + tid*132 + kq*4];
            ulonglong2 h0 = *(const ulonglong2*)&sm[K2_H + 0*128 + kq*4];
            ulonglong2 h1 = *(const ulonglong2*)&sm[K2_H + 1*128 + kq*4];
            ulonglong2 h2 = *(const ulonglong2*)&sm[K2_H + 2*128 + kq*4];
            ulonglong2 h3 = *(const ulonglong2*)&sm[K2_H + 3*128 + kq*4];
            q0 = ffma2(w.x, h0.x, q0); q0 = ffma2(w.y, h0.y, q0);
            q1 = ffma2(w.x, h1.x, q1); q1 = ffma2(w.y, h1.y, q1);
            q2 = ffma2(w.x, h2.x, q2); q2 = ffma2(w.y, h2.y, q2);
            q3 = ffma2(w.x, h3.x, q3); q3 = ffma2(w.y, h3.y, q3);
        }
#pragma unroll 4
        for (int kq = 0; kq < 16; kq++){
            ulonglong2 w  = *(const ulonglong2*)&sm[K2_WI + tid*68 + kq*4];
            ulonglong2 h0 = *(const ulonglong2*)&h1s[0*64 + kq*4];
            ulonglong2 h1 = *(const ulonglong2*)&h1s[1*64 + kq*4];
            ulonglong2 h2 = *(const ulonglong2*)&h1s[2*64 + kq*4];
            ulonglong2 h3 = *(const ulonglong2*)&h1s[3*64 + kq*4];
            q0 = ffma2(w.x, h0.x, q0); q0 = ffma2(w.y, h0.y, q0);
            q1 = ffma2(w.x, h1.x, q1); q1 = ffma2(w.y, h1.y, q1);
            q2 = ffma2(w.x, h2.x, q2); q2 = ffma2(w.y, h2.y, q2);
            q3 = ffma2(w.x, h3.x, q3); q3 = ffma2(w.y, h3.y, q3);
        }
        float bb = sm[K2_B + tid];
        float4 g4;
        g4.x = fsum2(q0) + bb; g4.y = fsum2(q1) + bb;
        g4.z = fsum2(q2) + bb; g4.w = fsum2(q3) + bb;
        *(float4*)&sm[K2_G + tid*4] = g4;
        __syncthreads();
        {
            float iv = sigf(sm[K2_G + (cj)*4 + crow]);
            float fv = sigf(sm[K2_G + (64+cj)*4 + crow]);
            float gv = tanhf_(sm[K2_G + (128+cj)*4 + crow]);
            float ov = sigf(sm[K2_G + (192+cj)*4 + crow]);
            float c = fv * creg + iv * gv; creg = c;
            float hv = ov * tanhf_(c);
            int off = crow*128 + d0 + cj;
            sm[K2_H + off] = hv;
            st_remote(peer_h + (unsigned)off*4u, hv);
            __stcg(&H2buf[(size_t)t*BB*128 + (b0+crow)*128 + d0 + cj], hv);
        }
        CLUSTER_SYNC();
    }
    out[OFF_C2 + (b0+crow)*128 + d0 + cj] = creg;
    if (r == 0){
        for (int i = tid; i < 512; i += 256)
            out[OFF_H2 + (b0 + (i>>7))*128 + (i & 127)] = sm[K2_H + i];
    }
}

// ===================== k3: layer-3 recurrence, per-group barriers =====================
#define K3_WH 0
#define K3_WI 8320
#define K3_B  12544
#define K3_SD 12576
#define K3_SE 29216
#define K3_FL 46112

__global__ void __launch_bounds__(512,1) k3_l3(
    const float* __restrict__ h3in, const float* __restrict__ c3in,
    const float* __restrict__ Wih3, const float* __restrict__ Whh3,
    const float* __restrict__ bih3, const float* __restrict__ bhh3,
    float* __restrict__ out)
{
    extern __shared__ float sm[];
    const unsigned smb = smem_u32(sm);
    const int tid = threadIdx.x;
    const int cta = blockIdx.x;
    const int b3 = cta >> 5, g3 = cta & 31;
    const int grp = b3, sub = (cta >> 3) & 3;
    const int warp = tid >> 5, lane = tid & 31;
    const int row = (warp & 7)*8 + (lane >> 2);      // 0..63
    const int jj  = (warp >> 3)*4 + (lane & 3);      // 0..7

    for (int i = tid; i < 32*256; i += 512){
        int rW = i >> 8, k = i & 255;
        int grow = (rW >> 3)*256 + g3*8 + (rW & 7);
        sm[K3_WH + rW*260 + k] = Whh3[grow*256 + k];
    }
    for (int i = tid; i < 32*128; i += 512){
        int rW = i >> 7, k = i & 127;
        int grow = (rW >> 3)*256 + g3*8 + (rW & 7);
        sm[K3_WI + rW*132 + k] = Wih3[grow*128 + k];
    }
    if (tid < 32){
        int grow = (tid >> 3)*256 + g3*8 + (tid & 7);
        sm[K3_B + tid] = bih3[grow] + bhh3[grow];
    }
    float creg = c3in[(b3*64 + row)*256 + g3*8 + jj];
    // publish h3 slot 0 (each CTA: its 2 rows of the group's 64)
    {
        int r2 = g3*2 + (tid >> 8), col = tid & 255;
        __stcg(&H3buf[(size_t)(b3*64 + r2)*256 + col], h3in[(b3*64 + r2)*256 + col]);
    }
    // prefetch h2[0]
    for (int i = tid; i < 2048; i += 512)
        cpa16(smb + (unsigned)(K3_SE + (i>>5)*132 + (i&31)*4)*4u,
              &H2buf[(size_t)(b3*64 + (i>>5))*128 + (i&31)*4]);
    CP_COMMIT();
    gbar3(tid, grp, sub);

    const int wr0 = (0*8 + jj)*260, wr1 = (1*8 + jj)*260, wr2 = (2*8 + jj)*260, wr3 = (3*8 + jj)*260;
    const int vr0 = (0*8 + jj)*132, vr1 = (1*8 + jj)*132, vr2 = (2*8 + jj)*132, vr3 = (3*8 + jj)*132;

    for (int t = 0; t < TT; t++){
        // issue h3[t] tile
        {
            const float* gp = &H3buf[(size_t)t*BB*256 + (b3*64)*256];
            for (int i = tid; i < 4096; i += 512)
                cpa16(smb + (unsigned)(K3_SD + (i>>6)*260 + (i&63)*4)*4u, gp + i*4);
        }
        CP_COMMIT();
        CP_WAIT1();                 // h2[t] ready (h3[t] in flight)
        __syncthreads();

        unsigned long long q0=0ull,q1=0ull,q2=0ull,q3=0ull;
        const float* hi = &sm[K3_SE + (t&1)*8448 + row*132];
#pragma unroll 4
        for (int kq = 0; kq < 32; kq++){
            ulonglong2 h = *(const ulonglong2*)&hi[kq*4];
            ulonglong2 w0 = *(const ulonglong2*)&sm[K3_WI + vr0 + kq*4];
            ulonglong2 w1 = *(const ulonglong2*)&sm[K3_WI + vr1 + kq*4];
            ulonglong2 w2 = *(const ulonglong2*)&sm[K3_WI + vr2 + kq*4];
            ulonglong2 w3 = *(const ulonglong2*)&sm[K3_WI + vr3 + kq*4];
            q0 = ffma2(w0.x, h.x, q0); q0 = ffma2(w0.y, h.y, q0);
            q1 = ffma2(w1.x, h.x, q1); q1 = ffma2(w1.y, h.y, q1);
            q2 = ffma2(w2.x, h.x, q2); q2 = ffma2(w2.y, h.y, q2);
            q3 = ffma2(w3.x, h.x, q3); q3 = ffma2(w3.y, h.y, q3);
        }
        // prefetch h2[t+1]
        if (t < TT-1){
            const float* gp = &H2buf[(size_t)(t+1)*BB*128 + (b3*64)*128];
            for (int i = tid; i < 2048; i += 512)
                cpa16(smb + (unsigned)(K3_SE + ((t+1)&1)*8448 + (i>>5)*132 + (i&31)*4)*4u, gp + i*4);
        }
        CP_COMMIT();
        CP_WAIT1();                 // h3[t] ready (h2[t+1] in flight)
        __syncthreads();

        const float* hh = &sm[K3_SD + row*260];
#pragma unroll 4
        for (int kq = 0; kq < 64; kq++){
            ulonglong2 h = *(const ulonglong2*)&hh[kq*4];
            ulonglong2 w0 = *(const ulonglong2*)&sm[K3_WH + wr0 + kq*4];
            ulonglong2 w1 = *(const ulonglong2*)&sm[K3_WH + wr1 + kq*4];
            ulonglong2 w2 = *(const ulonglong2*)&sm[K3_WH + wr2 + kq*4];
            ulonglong2 w3 = *(const ulonglong2*)&sm[K3_WH + wr3 + kq*4];
            q0 = ffma2(w0.x, h.x, q0); q0 = ffma2(w0.y, h.y, q0);
            q1 = ffma2(w1.x, h.x, q1); q1 = ffma2(w1.y, h.y, q1);
            q2 = ffma2(w2.x, h.x, q2); q2 = ffma2(w2.y, h.y, q2);
            q3 = ffma2(w3.x, h.x, q3); q3 = ffma2(w3.y, h.y, q3);
        }
        float a0 = fsum2(q0) + sm[K3_B + jj];
        float a1 = fsum2(q1) + sm[K3_B + 8 + jj];
        float a2 = fsum2(q2) + sm[K3_B + 16 + jj];
        float a3 = fsum2(q3) + sm[K3_B + 24 + jj];
        float c = sigf(a1)*creg + sigf(a0)*tanhf_(a2); creg = c;
        float hv = sigf(a3)*tanhf_(c);
        __stcg(&H3buf[(size_t)(t+1)*BB*256 + (b3*64 + row)*256 + g3*8 + jj], hv);
        if (t == TT-1){
            out[OFF_H3 + (b3*64 + row)*256 + g3*8 + jj] = hv;
            out[OFF_C3 + (b3*64 + row)*256 + g3*8 + jj] = creg;
        }
        gbar3(tid, grp, sub);
    }
}

// ===================== fc head (ffma2) =====================
#define FW1 0
#define FW2 33280
#define FB1 33408
#define FB2 33536
#define FHS 33540
#define FC_FL 37700

__global__ void __launch_bounds__(256,1) fc_kernel(
    const float* __restrict__ Wfc1, const float* __restrict__ bfc1,
    const float* __restrict__ Wfc2, const float* __restrict__ bfc2,
    float* __restrict__ out)
{
    extern __shared__ float sm[];
    const int tid = threadIdx.x, lane = tid & 31, warp = tid >> 5;
    const int t = blockIdx.x >> 1, half = blockIdx.x & 1;

    for (int i = tid; i < 128*256; i += 256)
        sm[FW1 + (i>>8)*260 + (i&255)] = Wfc1[i];
    if (tid < 128){ sm[FW2+tid] = Wfc2[tid]; sm[FB1+tid] = bfc1[tid]; }
    if (tid == 0) sm[FB2] = bfc2[0];
    __syncthreads();

    float* hrow = &sm[FHS + warp*2*260];
    for (int it = 0; it < 8; it++){
        const int r0 = half*128 + it*16 + warp*2;
        const float* g0 = &H3buf[(size_t)(t+1)*BB*256 + r0*256];
        for (int kk = lane; kk < 128; kk += 32){
            int rw = kk >> 6, col = (kk & 63)*4;
            *(float4*)&hrow[rw*260 + col] = __ldcg((const float4*)&g0[rw*256 + col]);
        }
        __syncwarp();
        unsigned long long q00=0ull,q01=0ull,q02=0ull,q03=0ull;
        unsigned long long q10=0ull,q11=0ull,q12=0ull,q13=0ull;
#pragma unroll 4
        for (int kq = 0; kq < 64; kq++){
            ulonglong2 h0 = *(const ulonglong2*)&hrow[kq*4];
            ulonglong2 h1 = *(const ulonglong2*)&hrow[260 + kq*4];
            ulonglong2 w0 = *(const ulonglong2*)&sm[FW1 + (lane)*260 + kq*4];
            ulonglong2 w1 = *(const ulonglong2*)&sm[FW1 + (lane+32)*260 + kq*4];
            ulonglong2 w2 = *(const ulonglong2*)&sm[FW1 + (lane+64)*260 + kq*4];
            ulonglong2 w3 = *(const ulonglong2*)&sm[FW1 + (lane+96)*260 + kq*4];
            q00 = ffma2(w0.x, h0.x, q00); q00 = ffma2(w0.y, h0.y, q00);
            q01 = ffma2(w1.x, h0.x, q01); q01 = ffma2(w1.y, h0.y, q01);
            q02 = ffma2(w2.x, h0.x, q02); q02 = ffma2(w2.y, h0.y, q02);
            q03 = ffma2(w3.x, h0.x, q03); q03 = ffma2(w3.y, h0.y, q03);
            q10 = ffma2(w0.x, h1.x, q10); q10 = ffma2(w0.y, h1.y, q10);
            q11 = ffma2(w1.x, h1.x, q11); q11 = ffma2(w1.y, h1.y, q11);
            q12 = ffma2(w2.x, h1.x, q12); q12 = ffma2(w2.y, h1.y, q12);
            q13 = ffma2(w3.x, h1.x, q13); q13 = ffma2(w3.y, h1.y, q13);
        }
        float f00 = fsum2(q00)+sm[FB1+lane],    f01 = fsum2(q01)+sm[FB1+lane+32];
        float f02 = fsum2(q02)+sm[FB1+lane+64], f03 = fsum2(q03)+sm[FB1+lane+96];
        float f10 = fsum2(q10)+sm[FB1+lane],    f11 = fsum2(q11)+sm[FB1+lane+32];
        float f12 = fsum2(q12)+sm[FB1+lane+64], f13 = fsum2(q13)+sm[FB1+lane+96];
        float s0 = fmaxf(f00,0.f)*sm[FW2+lane] + fmaxf(f01,0.f)*sm[FW2+lane+32]
                 + fmaxf(f02,0.f)*sm[FW2+lane+64] + fmaxf(f03,0.f)*sm[FW2+lane+96];
        float s1 = fmaxf(f10,0.f)*sm[FW2+lane] + fmaxf(f11,0.f)*sm[FW2+lane+32]
                 + fmaxf(f12,0.f)*sm[FW2+lane+64] + fmaxf(f13,0.f)*sm[FW2+lane+96];
#pragma unroll
        for (int o = 16; o; o >>= 1){
            s0 += __shfl_xor_sync(0xffffffffu, s0, o);
            s1 += __shfl_xor_sync(0xffffffffu, s1, o);
        }
        if (lane == 0){
            out[OFF_Y + t*BB + r0]     = s0 + sm[FB2];
            out[OFF_Y + t*BB + r0 + 1] = s1 + sm[FB2];
        }
        __syncwarp();
    }
}

extern "C" void kernel_launch(void* const* d_in, const int* in_sizes, int n_in,
                              void* d_out, int out_size)
{
    const float* x    = (const float*)d_in[0];
    const float* h1   = (const float*)d_in[1];
    const float* c1   = (const float*)d_in[2];
    const float* h2   = (const float*)d_in[3];
    const float* c2   = (const float*)d_in[4];
    const float* h3   = (const float*)d_in[5];
    const float* c3   = (const float*)d_in[6];
    const float* Wih1 = (const float*)d_in[7];
    const float* Whh1 = (const float*)d_in[8];
    const float* bih1 = (const float*)d_in[9];
    const float* bhh1 = (const float*)d_in[10];
    const float* Wih2 = (const float*)d_in[11];
    const float* Whh2 = (const float*)d_in[12];
    const float* bih2 = (const float*)d_in[13];
    const float* bhh2 = (const float*)d_in[14];
    const float* Wih3 = (const float*)d_in[15];
    const float* Whh3 = (const float*)d_in[16];
    const float* bih3 = (const float*)d_in[17];
    const float* bhh3 = (const float*)d_in[18];
    const float* Wfc1 = (const float*)d_in[19];
    const float* bfc1 = (const float*)d_in[20];
    const float* Wfc2 = (const float*)d_in[21];
    const float* bfc2 = (const float*)d_in[22];
    float* out = (float*)d_out;

    cudaFuncSetAttribute(k1_l1, cudaFuncAttributeMaxDynamicSharedMemorySize, K1_FL*4);
    cudaFuncSetAttribute(k2_l2, cudaFuncAttributeMaxDynamicSharedMemorySize, K2_FL*4);
    cudaFuncSetAttribute(k3_l3, cudaFuncAttributeMaxDynamicSharedMemorySize, K3_FL*4);
    cudaFuncSetAttribute(fc_kernel, cudaFuncAttributeMaxDynamicSharedMemorySize, FC_FL*4);

    k1_l1<<<128, 256, K1_FL*4>>>(x, h1, c1, Wih1, Whh1, bih1, bhh1, out);
    k2_l2<<<128, 256, K2_FL*4>>>(h2, c2, Wih2, Whh2, bih2, bhh2, out);
    k3_l3<<<128, 512, K3_FL*4>>>(h3, c3, Wih3, Whh3, bih3, bhh3, out);
    fc_kernel<<<1024, 256, FC_FL*4>>>(Wfc1, bfc1, Wfc2, bfc2, out);
}